// round 12
// baseline (speedup 1.0000x reference)
#include <cuda_runtime.h>
#include <cuda_bf16.h>
#include <cstdint>

#define NN 12288
#define EE 196608
#define FIN 1433
#define NST16 90           // 90 k16-steps: 90*16 = 1440 >= 1433
#define KSPL 5             // split-K factor: 5 * 18 steps
#define SPS 18             // k16-steps per split
#define H1 32
#define H2 16
#define NC 7

// ---------------- scratch (zero-initialized at load; self-cleaning per run) ----------------
__device__ __align__(16) float g_y[NN * H1];    // y = x@W1 (unscaled); reset by k_h_z
__device__ __align__(16) float g_acc[NN * H1];  // GCN edge accum;      reset by k_h_z
__device__ __align__(16) float g_h[NN * H1];    // overwritten every run
__device__ __align__(16) float g_z[NN * H2];    // overwritten every run
__device__ __align__(16) float g_sga[NN * H2];  // SAGE sum;            reset by k_head
__device__ int   g_deg[NN];                     // in-degree (no self-loop); reset by k_h_z
__device__ int   g_cnt[NN];                     // out-degree;          reset by k_head
// W1^T split bf16 hi/lo, packed in B-fragment order (overwritten every run)
__device__ __align__(16) __nv_bfloat16 g_whp[NST16 * 32 * 32];
__device__ __align__(16) __nv_bfloat16 g_wlp[NST16 * 32 * 32];

// ---------------- helpers ----------------
__device__ __forceinline__ void red4(float* p, float4 v) {
    asm volatile("red.global.add.v4.f32 [%0], {%1,%2,%3,%4};"
                 :: "l"(p), "f"(v.x), "f"(v.y), "f"(v.z), "f"(v.w) : "memory");
}
__device__ __forceinline__ void red2(float* p, float a, float b) {
    asm volatile("red.global.add.v2.f32 [%0], {%1,%2};"
                 :: "l"(p), "f"(a), "f"(b) : "memory");
}

__device__ __forceinline__ void mma_bf16(float* c, const uint32_t* a,
                                         uint32_t b0, uint32_t b1) {
    asm volatile(
        "mma.sync.aligned.m16n8k16.row.col.f32.bf16.bf16.f32 "
        "{%0,%1,%2,%3}, {%4,%5,%6,%7}, {%8,%9}, {%0,%1,%2,%3};"
        : "+f"(c[0]), "+f"(c[1]), "+f"(c[2]), "+f"(c[3])
        : "r"(a[0]), "r"(a[1]), "r"(a[2]), "r"(a[3]), "r"(b0), "r"(b1));
}

__device__ __forceinline__ void split2(float c0, float c1, uint32_t& hi, uint32_t& lo) {
    __nv_bfloat162 hb = __floats2bfloat162_rn(c0, c1);
    float l0 = c0 - __bfloat162float(hb.x);
    float l1 = c1 - __bfloat162float(hb.y);
    __nv_bfloat162 lb = __floats2bfloat162_rn(l0, l1);
    hi = *(uint32_t*)&hb;
    lo = *(uint32_t*)&lb;
}

__device__ __forceinline__ int detect64(const void* ei, int* s_flag) {
    if (threadIdx.x < 32) {
        int ok = (((const int*)ei)[2 * threadIdx.x + 1] == 0);
        int all = __all_sync(0xffffffffu, ok);
        if (threadIdx.x == 0) *s_flag = all;
    }
    __syncthreads();
    return *s_flag;
}
__device__ __forceinline__ int eload(const void* ei, int is64, int which, int e) {
    if (is64) return (int)(((const long long*)ei)[(long long)which * EE + e]);
    return ((const int*)ei)[which * EE + e];
}

// ---------------- W split + pack (fragment order) ----------------
__global__ void k_wpack(const float* __restrict__ W1) {
    int idx = blockIdx.x * blockDim.x + threadIdx.x;   // NST16*32*32 range
    if (idx < NST16 * 32 * 32) {
        int c = idx >> 10, rem = idx & 1023;
        int n = rem >> 5, p = rem & 31;
        int q = p >> 2, j = p & 3;
        int k = c * 16 + 2 * q + (j & 1) + ((j >> 1) & 1) * 8;
        float w = (k < FIN) ? W1[k * H1 + n] : 0.f;
        __nv_bfloat16 hb = __float2bfloat16_rn(w);
        float lo = w - __bfloat162float(hb);
        g_whp[idx] = hb;
        g_wlp[idx] = __float2bfloat16_rn(lo);
    }
}

// -------- fused split-K HMMA GEMM (y += x@W1, unscaled) + edge histograms --------
// grid (96, 13): by<5 -> gemm, by>=5 -> 768 count blocks (scheduled after).
__device__ __forceinline__ void ldx8(const float* __restrict__ xr0,
                                     const float* __restrict__ xr1,
                                     int c0, float* f) {
    const bool m0 = (c0     < FIN), m1 = (c0 + 1 < FIN);
    const bool m8 = (c0 + 8 < FIN), m9 = (c0 + 9 < FIN);
    f[0] = m0 ? __ldg(xr0 + c0)     : 0.f;
    f[1] = m1 ? __ldg(xr0 + c0 + 1) : 0.f;
    f[2] = m0 ? __ldg(xr1 + c0)     : 0.f;
    f[3] = m1 ? __ldg(xr1 + c0 + 1) : 0.f;
    f[4] = m8 ? __ldg(xr0 + c0 + 8) : 0.f;
    f[5] = m9 ? __ldg(xr0 + c0 + 9) : 0.f;
    f[6] = m8 ? __ldg(xr1 + c0 + 8) : 0.f;
    f[7] = m9 ? __ldg(xr1 + c0 + 9) : 0.f;
}

__global__ void __launch_bounds__(256) k_gemm_count(const float* __restrict__ x,
                                                    const void* ei) {
    if (blockIdx.y >= KSPL) {
        // ---- histogram blocks: 8 rows x 96 = 768 blocks ----
        __shared__ int s64;
        int is64 = detect64(ei, &s64);
        int cb = (blockIdx.y - KSPL) * 96 + blockIdx.x;
        int e = cb * 256 + threadIdx.x;
        atomicAdd(&g_deg[eload(ei, is64, 1, e)], 1);
        atomicAdd(&g_cnt[eload(ei, is64, 0, e)], 1);
        return;
    }
    const int tid = threadIdx.x, wid = tid >> 5, lane = tid & 31;
    const int gid = lane >> 2;
    const int q   = lane & 3;
    const int t2  = q * 2;
    const int r0  = blockIdx.x * 128 + wid * 16 + gid;
    const int r1  = r0 + 8;
    const float* xr0 = x + (long long)r0 * FIN;
    const float* xr1 = x + (long long)r1 * FIN;
    const int sbase = blockIdx.y * SPS;

    float acc[4][4];
    #pragma unroll
    for (int nb = 0; nb < 4; nb++)
        #pragma unroll
        for (int p = 0; p < 4; p++) acc[nb][p] = 0.f;

    float cur[8], nxt[8];
    ldx8(xr0, xr1, sbase * 16 + t2, cur);

    for (int s = 0; s < SPS; s++) {
        const int c = sbase + s;
        if (s + 1 < SPS) ldx8(xr0, xr1, (c + 1) * 16 + t2, nxt);

        uint32_t ah[4], al[4];
        split2(cur[0], cur[1], ah[0], al[0]);
        split2(cur[2], cur[3], ah[1], al[1]);
        split2(cur[4], cur[5], ah[2], al[2]);
        split2(cur[6], cur[7], ah[3], al[3]);

        #pragma unroll
        for (int nb = 0; nb < 4; nb++) {
            const int n = nb * 8 + gid;
            const uint2 bh = __ldg((const uint2*)g_whp + (c * 32 + n) * 8 + q);
            const uint2 bl = __ldg((const uint2*)g_wlp + (c * 32 + n) * 8 + q);
            mma_bf16(acc[nb], ah, bh.x, bh.y);
            mma_bf16(acc[nb], al, bh.x, bh.y);
            mma_bf16(acc[nb], ah, bl.x, bl.y);
        }
        #pragma unroll
        for (int p = 0; p < 8; p++) cur[p] = nxt[p];
    }

    #pragma unroll
    for (int nb = 0; nb < 4; nb++) {
        red2(&g_y[r0 * H1 + nb * 8 + t2], acc[nb][0], acc[nb][1]);
        red2(&g_y[r1 * H1 + nb * 8 + t2], acc[nb][2], acc[nb][3]);
    }
}

// ------- GCN edge aggregation: acc[src] += dis[dst]*y[dst], 2 edges/thread -------
__global__ void k_gcn(const void* ei) {
    __shared__ int s64;
    int is64 = detect64(ei, &s64);
    int idx = blockIdx.x * blockDim.x + threadIdx.x;   // EE*4 threads
    int g  = idx & 7;
    int e0 = idx >> 3;
    int e1 = e0 + EE / 2;
    int r0 = eload(ei, is64, 0, e0), c0 = eload(ei, is64, 1, e0);
    int r1 = eload(ei, is64, 0, e1), c1 = eload(ei, is64, 1, e1);
    float s0 = rsqrtf((float)(g_deg[c0] + 1));
    float s1 = rsqrtf((float)(g_deg[c1] + 1));
    float4 v0 = *(const float4*)&g_y[c0 * H1 + g * 4];
    float4 v1 = *(const float4*)&g_y[c1 * H1 + g * 4];
    v0.x *= s0; v0.y *= s0; v0.z *= s0; v0.w *= s0;
    v1.x *= s1; v1.y *= s1; v1.z *= s1; v1.w *= s1;
    red4(&g_acc[r0 * H1 + g * 4], v0);
    red4(&g_acc[r1 * H1 + g * 4], v1);
}

// --- h = relu(dis*(acc + dis*y)+b1); z = h@Wr via smem (no shfl chain); self-clean ---
__global__ void __launch_bounds__(256) k_h_z(const float* __restrict__ b1,
                                             const float* __restrict__ Wr) {
    __shared__ float sh[8][H1 + 1];    // h rows for the block's 8 nodes (padded)
    __shared__ float sWr[H1 * H2];
    const int tid = threadIdx.x;
    const int wid = tid >> 5, lane = tid & 31;
    const int i = blockIdx.x * 8 + wid;

    // stage Wr (512 floats) with 256 threads
    sWr[tid] = __ldg(Wr + tid);
    sWr[tid + 256] = __ldg(Wr + tid + 256);

    const float di = rsqrtf((float)(g_deg[i] + 1));
    const float a  = g_acc[i * H1 + lane];
    const float yv = g_y[i * H1 + lane];
    const float hv = fmaxf(di * (a + di * yv) + __ldg(b1 + lane), 0.f);
    g_h[i * H1 + lane] = hv;
    sh[wid][lane] = hv;

    // self-clean for next graph replay (deg consumed by gcn already)
    g_acc[i * H1 + lane] = 0.f;
    g_y[i * H1 + lane]   = 0.f;
    if (lane == 0) g_deg[i] = 0;

    __syncthreads();

    // z[n][j] = sum_c sh[n][c] * sWr[c*16+j]; 128 threads, one per (n,j)
    if (tid < 128) {
        const int n = tid >> 4, j = tid & 15;
        float z = 0.f;
        #pragma unroll
        for (int c = 0; c < H1; c++)
            z += sh[n][c] * sWr[c * H2 + j];
        g_z[(blockIdx.x * 8 + n) * H2 + j] = z;
    }
}

// ------- SAGE aggregation of z (16-wide), 2 independent edges/thread -------
__global__ void k_sage(const void* ei) {
    __shared__ int s64;
    int is64 = detect64(ei, &s64);
    int idx = blockIdx.x * blockDim.x + threadIdx.x;   // EE*2 threads
    int g  = idx & 3;
    int e0 = idx >> 2;
    int e1 = e0 + EE / 2;
    int s0 = eload(ei, is64, 0, e0), d0 = eload(ei, is64, 1, e0);
    int s1 = eload(ei, is64, 0, e1), d1 = eload(ei, is64, 1, e1);
    float4 v0 = *(const float4*)&g_z[d0 * H2 + g * 4];
    float4 v1 = *(const float4*)&g_z[d1 * H2 + g * 4];
    red4(&g_sga[s0 * H2 + g * 4], v0);
    red4(&g_sga[s1 * H2 + g * 4], v1);
}

// ---------------- head (resets cnt/sga) ----------------
__global__ void __launch_bounds__(256) k_head(const float* __restrict__ Wl,
                                              const float* __restrict__ bl,
                                              const float* __restrict__ br,
                                              const float* __restrict__ W3,
                                              const float* __restrict__ b3,
                                              float* __restrict__ out) {
    __shared__ float sWl[H1 * H2], sW3[H2 * NC];
    __shared__ float sbl[H2], sbr[H2], sb3[NC];
    const int tid = threadIdx.x;
    for (int i = tid; i < H1 * H2; i += blockDim.x) sWl[i] = Wl[i];
    for (int i = tid; i < H2 * NC; i += blockDim.x) sW3[i] = W3[i];
    if (tid < H2) { sbl[tid] = bl[tid]; sbr[tid] = br[tid]; }
    if (tid < NC) sb3[tid] = b3[tid];
    __syncthreads();

    const int n = blockIdx.x * blockDim.x + tid;
    if (n >= NN) return;
    const float invc = 1.0f / fmaxf((float)g_cnt[n], 1.0f);
    g_cnt[n] = 0;   // self-clean

    float t[H2];
    #pragma unroll
    for (int j = 0; j < H2; j++) {
        t[j] = sbl[j] + sbr[j] + g_sga[n * H2 + j] * invc;
        g_sga[n * H2 + j] = 0.f;   // self-clean
    }
    #pragma unroll 4
    for (int c = 0; c < H1; c++) {
        const float hv = g_h[n * H1 + c];
        #pragma unroll
        for (int j = 0; j < H2; j++)
            t[j] += hv * sWl[c * H2 + j];
    }
    float ss = 0.f;
    #pragma unroll
    for (int j = 0; j < H2; j++) { t[j] = fmaxf(t[j], 0.f); ss += t[j] * t[j]; }
    const float sc = 1.0f / (sqrtf(ss) + 1e-6f);

    float lg[NC];
    #pragma unroll
    for (int k = 0; k < NC; k++) lg[k] = sb3[k];
    #pragma unroll
    for (int j = 0; j < H2; j++) {
        const float tv = t[j] * sc;
        #pragma unroll
        for (int k = 0; k < NC; k++) lg[k] += tv * sW3[j * NC + k];
    }
    float mx = lg[0];
    #pragma unroll
    for (int k = 1; k < NC; k++) mx = fmaxf(mx, lg[k]);
    float se = 0.f;
    #pragma unroll
    for (int k = 0; k < NC; k++) { lg[k] = __expf(lg[k] - mx); se += lg[k]; }
    const float inv = 1.0f / se;
    #pragma unroll
    for (int k = 0; k < NC; k++) out[n * NC + k] = lg[k] * inv;
}

extern "C" void kernel_launch(void* const* d_in, const int* in_sizes, int n_in,
                              void* d_out, int out_size) {
    const float* x  = (const float*)d_in[0];
    const void*  ei = d_in[1];
    const float* W1 = (const float*)d_in[2];
    const float* b1 = (const float*)d_in[3];
    const float* Wl = (const float*)d_in[4];
    const float* bl = (const float*)d_in[5];
    const float* Wr = (const float*)d_in[6];
    const float* br = (const float*)d_in[7];
    const float* W3 = (const float*)d_in[8];
    const float* b3 = (const float*)d_in[9];
    float* out = (float*)d_out;

    k_wpack<<<360, 256>>>(W1);
    k_gemm_count<<<dim3(96, KSPL + 8), 256>>>(x, ei);
    k_gcn<<<(EE * 4) / 256, 256>>>(ei);
    k_h_z<<<NN / 8, 256>>>(b1, Wr);
    k_sage<<<(EE * 2) / 256, 256>>>(ei);
    k_head<<<(NN + 255) / 256, 256>>>(Wl, bl, br, W3, b3, out);
}

// round 14
// speedup vs baseline: 1.1678x; 1.1678x over previous
#include <cuda_runtime.h>
#include <cuda_bf16.h>
#include <cstdint>

#define NN 12288
#define EE 196608
#define FIN 1433
#define NST16 90           // 90 k16-steps: 90*16 = 1440 >= 1433
#define KSPL 5             // split-K factor: 5 * 18 steps
#define SPS 18             // k16-steps per split
#define H1 32
#define H2 16
#define NC 7

// PDL: wait for programmatic predecessor's memory to be visible
#define GDC_WAIT() asm volatile("griddepcontrol.wait;" ::: "memory")

// ---------------- scratch (zero-initialized at load; self-cleaning per run) ----------------
__device__ __align__(16) float g_y[NN * H1];    // y = x@W1 (unscaled); reset by k_h_z
__device__ __align__(16) float g_acc[NN * H1];  // GCN edge accum;      reset by k_h_z
__device__ __align__(16) float g_h[NN * H1];    // overwritten every run
__device__ __align__(16) float g_z[NN * H2];    // overwritten every run
__device__ __align__(16) float g_sga[NN * H2];  // SAGE sum;            reset by k_head
__device__ int   g_deg[NN];                     // in-degree (no self-loop); reset by k_h_z
__device__ int   g_cnt[NN];                     // out-degree;          reset by k_head
// W1^T split bf16 hi/lo, packed in B-fragment order (overwritten every run)
__device__ __align__(16) __nv_bfloat16 g_whp[NST16 * 32 * 32];
__device__ __align__(16) __nv_bfloat16 g_wlp[NST16 * 32 * 32];

// ---------------- helpers ----------------
__device__ __forceinline__ void red4(float* p, float4 v) {
    asm volatile("red.global.add.v4.f32 [%0], {%1,%2,%3,%4};"
                 :: "l"(p), "f"(v.x), "f"(v.y), "f"(v.z), "f"(v.w) : "memory");
}
__device__ __forceinline__ void red2(float* p, float a, float b) {
    asm volatile("red.global.add.v2.f32 [%0], {%1,%2};"
                 :: "l"(p), "f"(a), "f"(b) : "memory");
}

__device__ __forceinline__ void mma_bf16(float* c, const uint32_t* a,
                                         uint32_t b0, uint32_t b1) {
    asm volatile(
        "mma.sync.aligned.m16n8k16.row.col.f32.bf16.bf16.f32 "
        "{%0,%1,%2,%3}, {%4,%5,%6,%7}, {%8,%9}, {%0,%1,%2,%3};"
        : "+f"(c[0]), "+f"(c[1]), "+f"(c[2]), "+f"(c[3])
        : "r"(a[0]), "r"(a[1]), "r"(a[2]), "r"(a[3]), "r"(b0), "r"(b1));
}

__device__ __forceinline__ void split2(float c0, float c1, uint32_t& hi, uint32_t& lo) {
    __nv_bfloat162 hb = __floats2bfloat162_rn(c0, c1);
    float l0 = c0 - __bfloat162float(hb.x);
    float l1 = c1 - __bfloat162float(hb.y);
    __nv_bfloat162 lb = __floats2bfloat162_rn(l0, l1);
    hi = *(uint32_t*)&hb;
    lo = *(uint32_t*)&lb;
}

__device__ __forceinline__ int detect64(const void* ei, int* s_flag) {
    if (threadIdx.x < 32) {
        int ok = (((const int*)ei)[2 * threadIdx.x + 1] == 0);
        int all = __all_sync(0xffffffffu, ok);
        if (threadIdx.x == 0) *s_flag = all;
    }
    __syncthreads();
    return *s_flag;
}
__device__ __forceinline__ int eload(const void* ei, int is64, int which, int e) {
    if (is64) return (int)(((const long long*)ei)[(long long)which * EE + e]);
    return ((const int*)ei)[which * EE + e];
}

// ---------------- W split + pack (fragment order); plain launch ----------------
__global__ void k_wpack(const float* __restrict__ W1) {
    int idx = blockIdx.x * blockDim.x + threadIdx.x;   // NST16*32*32 range
    if (idx < NST16 * 32 * 32) {
        int c = idx >> 10, rem = idx & 1023;
        int n = rem >> 5, p = rem & 31;
        int q = p >> 2, j = p & 3;
        int k = c * 16 + 2 * q + (j & 1) + ((j >> 1) & 1) * 8;
        float w = (k < FIN) ? W1[k * H1 + n] : 0.f;
        __nv_bfloat16 hb = __float2bfloat16_rn(w);
        float lo = w - __bfloat162float(hb);
        g_whp[idx] = hb;
        g_wlp[idx] = __float2bfloat16_rn(lo);
    }
}

// -------- fused split-K HMMA GEMM (y += x@W1) + edge histograms (PDL on wpack) --------
// grid (96, 13): by<5 -> gemm (waits for W), by>=5 -> count blocks (no wait needed).
__device__ __forceinline__ void ldx8(const float* __restrict__ xr0,
                                     const float* __restrict__ xr1,
                                     int c0, float* f) {
    const bool m0 = (c0     < FIN), m1 = (c0 + 1 < FIN);
    const bool m8 = (c0 + 8 < FIN), m9 = (c0 + 9 < FIN);
    f[0] = m0 ? __ldg(xr0 + c0)     : 0.f;
    f[1] = m1 ? __ldg(xr0 + c0 + 1) : 0.f;
    f[2] = m0 ? __ldg(xr1 + c0)     : 0.f;
    f[3] = m1 ? __ldg(xr1 + c0 + 1) : 0.f;
    f[4] = m8 ? __ldg(xr0 + c0 + 8) : 0.f;
    f[5] = m9 ? __ldg(xr0 + c0 + 9) : 0.f;
    f[6] = m8 ? __ldg(xr1 + c0 + 8) : 0.f;
    f[7] = m9 ? __ldg(xr1 + c0 + 9) : 0.f;
}

__global__ void __launch_bounds__(256) k_gemm_count(const float* __restrict__ x,
                                                    const void* ei) {
    if (blockIdx.y >= KSPL) {
        // ---- histogram blocks: touch only ei/deg/cnt -> never need the wait ----
        __shared__ int s64;
        int is64 = detect64(ei, &s64);
        int cb = (blockIdx.y - KSPL) * 96 + blockIdx.x;
        int e = cb * 256 + threadIdx.x;
        atomicAdd(&g_deg[eload(ei, is64, 1, e)], 1);
        atomicAdd(&g_cnt[eload(ei, is64, 0, e)], 1);
        return;
    }
    const int tid = threadIdx.x, wid = tid >> 5, lane = tid & 31;
    const int gid = lane >> 2;
    const int q   = lane & 3;
    const int t2  = q * 2;
    const int r0  = blockIdx.x * 128 + wid * 16 + gid;
    const int r1  = r0 + 8;
    const float* xr0 = x + (long long)r0 * FIN;
    const float* xr1 = x + (long long)r1 * FIN;
    const int sbase = blockIdx.y * SPS;

    float acc[4][4];
    #pragma unroll
    for (int nb = 0; nb < 4; nb++)
        #pragma unroll
        for (int p = 0; p < 4; p++) acc[nb][p] = 0.f;

    float cur[8], nxt[8];
    ldx8(xr0, xr1, sbase * 16 + t2, cur);   // pre-wait prefetch of x
    GDC_WAIT();                             // W pack must be visible beyond here

    for (int s = 0; s < SPS; s++) {
        const int c = sbase + s;
        if (s + 1 < SPS) ldx8(xr0, xr1, (c + 1) * 16 + t2, nxt);

        uint32_t ah[4], al[4];
        split2(cur[0], cur[1], ah[0], al[0]);
        split2(cur[2], cur[3], ah[1], al[1]);
        split2(cur[4], cur[5], ah[2], al[2]);
        split2(cur[6], cur[7], ah[3], al[3]);

        #pragma unroll
        for (int nb = 0; nb < 4; nb++) {
            const int n = nb * 8 + gid;
            const uint2 bh = __ldg((const uint2*)g_whp + (c * 32 + n) * 8 + q);
            const uint2 bl = __ldg((const uint2*)g_wlp + (c * 32 + n) * 8 + q);
            mma_bf16(acc[nb], ah, bh.x, bh.y);
            mma_bf16(acc[nb], al, bh.x, bh.y);
            mma_bf16(acc[nb], ah, bl.x, bl.y);
        }
        #pragma unroll
        for (int p = 0; p < 8; p++) cur[p] = nxt[p];
    }

    #pragma unroll
    for (int nb = 0; nb < 4; nb++) {
        red2(&g_y[r0 * H1 + nb * 8 + t2], acc[nb][0], acc[nb][1]);
        red2(&g_y[r1 * H1 + nb * 8 + t2], acc[nb][2], acc[nb][3]);
    }
}

// ------- GCN edge aggregation (PDL on gemm_count): prefetch indices pre-wait -------
__global__ void k_gcn(const void* ei) {
    __shared__ int s64;
    int is64 = detect64(ei, &s64);
    int idx = blockIdx.x * blockDim.x + threadIdx.x;   // EE*4 threads
    int g  = idx & 7;
    int e0 = idx >> 3;
    int e1 = e0 + EE / 2;
    int r0 = eload(ei, is64, 0, e0), c0 = eload(ei, is64, 1, e0);
    int r1 = eload(ei, is64, 0, e1), c1 = eload(ei, is64, 1, e1);
    GDC_WAIT();                             // deg / y visible beyond here
    float s0 = rsqrtf((float)(g_deg[c0] + 1));
    float s1 = rsqrtf((float)(g_deg[c1] + 1));
    float4 v0 = *(const float4*)&g_y[c0 * H1 + g * 4];
    float4 v1 = *(const float4*)&g_y[c1 * H1 + g * 4];
    v0.x *= s0; v0.y *= s0; v0.z *= s0; v0.w *= s0;
    v1.x *= s1; v1.y *= s1; v1.z *= s1; v1.w *= s1;
    red4(&g_acc[r0 * H1 + g * 4], v0);
    red4(&g_acc[r1 * H1 + g * 4], v1);
}

// --- h = relu(dis*(acc + dis*y)+b1); z = h@Wr via smem (PDL on gcn); self-clean ---
__global__ void __launch_bounds__(256) k_h_z(const float* __restrict__ b1,
                                             const float* __restrict__ Wr) {
    __shared__ float sh[8][H1 + 1];    // h rows for the block's 8 nodes (padded)
    __shared__ float sWr[H1 * H2];
    const int tid = threadIdx.x;
    const int wid = tid >> 5, lane = tid & 31;
    const int i = blockIdx.x * 8 + wid;

    // pre-wait: stage Wr + b1 (kernel inputs, written before the graph ran)
    sWr[tid] = __ldg(Wr + tid);
    sWr[tid + 256] = __ldg(Wr + tid + 256);
    const float bv = __ldg(b1 + lane);
    GDC_WAIT();                             // acc / deg / y visible beyond here

    const float di = rsqrtf((float)(g_deg[i] + 1));
    const float a  = g_acc[i * H1 + lane];
    const float yv = g_y[i * H1 + lane];
    const float hv = fmaxf(di * (a + di * yv) + bv, 0.f);
    g_h[i * H1 + lane] = hv;
    sh[wid][lane] = hv;

    // self-clean for next graph replay (deg consumed by gcn already)
    g_acc[i * H1 + lane] = 0.f;
    g_y[i * H1 + lane]   = 0.f;
    if (lane == 0) g_deg[i] = 0;

    __syncthreads();

    // z[n][j] = sum_c sh[n][c] * sWr[c*16+j]; 128 threads, one per (n,j)
    if (tid < 128) {
        const int n = tid >> 4, j = tid & 15;
        float z = 0.f;
        #pragma unroll
        for (int c = 0; c < H1; c++)
            z += sh[n][c] * sWr[c * H2 + j];
        g_z[(blockIdx.x * 8 + n) * H2 + j] = z;
    }
}

// ------- SAGE aggregation of z (PDL on h_z): prefetch indices pre-wait -------
__global__ void k_sage(const void* ei) {
    __shared__ int s64;
    int is64 = detect64(ei, &s64);
    int idx = blockIdx.x * blockDim.x + threadIdx.x;   // EE*2 threads
    int g  = idx & 3;
    int e0 = idx >> 2;
    int e1 = e0 + EE / 2;
    int s0 = eload(ei, is64, 0, e0), d0 = eload(ei, is64, 1, e0);
    int s1 = eload(ei, is64, 0, e1), d1 = eload(ei, is64, 1, e1);
    GDC_WAIT();                             // z visible beyond here
    float4 v0 = *(const float4*)&g_z[d0 * H2 + g * 4];
    float4 v1 = *(const float4*)&g_z[d1 * H2 + g * 4];
    red4(&g_sga[s0 * H2 + g * 4], v0);
    red4(&g_sga[s1 * H2 + g * 4], v1);
}

// ---------------- head (PDL on sage; resets cnt/sga) ----------------
__global__ void __launch_bounds__(256) k_head(const float* __restrict__ Wl,
                                              const float* __restrict__ bl,
                                              const float* __restrict__ br,
                                              const float* __restrict__ W3,
                                              const float* __restrict__ b3,
                                              float* __restrict__ out) {
    __shared__ float sWl[H1 * H2], sW3[H2 * NC];
    __shared__ float sbl[H2], sbr[H2], sb3[NC];
    const int tid = threadIdx.x;
    // pre-wait: stage weights (kernel inputs)
    for (int i = tid; i < H1 * H2; i += blockDim.x) sWl[i] = Wl[i];
    for (int i = tid; i < H2 * NC; i += blockDim.x) sW3[i] = W3[i];
    if (tid < H2) { sbl[tid] = bl[tid]; sbr[tid] = br[tid]; }
    if (tid < NC) sb3[tid] = b3[tid];
    __syncthreads();
    GDC_WAIT();                             // sga / cnt / h visible beyond here

    const int n = blockIdx.x * blockDim.x + tid;
    if (n >= NN) return;
    const float invc = 1.0f / fmaxf((float)g_cnt[n], 1.0f);
    g_cnt[n] = 0;   // self-clean

    float t[H2];
    #pragma unroll
    for (int j = 0; j < H2; j++) {
        t[j] = sbl[j] + sbr[j] + g_sga[n * H2 + j] * invc;
        g_sga[n * H2 + j] = 0.f;   // self-clean
    }
    #pragma unroll 4
    for (int c = 0; c < H1; c++) {
        const float hv = g_h[n * H1 + c];
        #pragma unroll
        for (int j = 0; j < H2; j++)
            t[j] += hv * sWl[c * H2 + j];
    }
    float ss = 0.f;
    #pragma unroll
    for (int j = 0; j < H2; j++) { t[j] = fmaxf(t[j], 0.f); ss += t[j] * t[j]; }
    const float sc = 1.0f / (sqrtf(ss) + 1e-6f);

    float lg[NC];
    #pragma unroll
    for (int k = 0; k < NC; k++) lg[k] = sb3[k];
    #pragma unroll
    for (int j = 0; j < H2; j++) {
        const float tv = t[j] * sc;
        #pragma unroll
        for (int k = 0; k < NC; k++) lg[k] += tv * sW3[j * NC + k];
    }
    float mx = lg[0];
    #pragma unroll
    for (int k = 1; k < NC; k++) mx = fmaxf(mx, lg[k]);
    float se = 0.f;
    #pragma unroll
    for (int k = 0; k < NC; k++) { lg[k] = __expf(lg[k] - mx); se += lg[k]; }
    const float inv = 1.0f / se;
    #pragma unroll
    for (int k = 0; k < NC; k++) out[n * NC + k] = lg[k] * inv;
}

// ---------------- host: PDL launch helper ----------------
template <typename F, typename... Args>
static void launch_pdl(F f, dim3 grid, dim3 block, Args... args) {
    cudaLaunchConfig_t cfg = {};
    cfg.gridDim = grid;
    cfg.blockDim = block;
    cfg.dynamicSmemBytes = 0;
    cfg.stream = 0;
    cudaLaunchAttribute at[1];
    at[0].id = cudaLaunchAttributeProgrammaticStreamSerialization;
    at[0].val.programmaticStreamSerializationAllowed = 1;
    cfg.attrs = at;
    cfg.numAttrs = 1;
    cudaLaunchKernelEx(&cfg, f, args...);
}

extern "C" void kernel_launch(void* const* d_in, const int* in_sizes, int n_in,
                              void* d_out, int out_size) {
    const float* x  = (const float*)d_in[0];
    const void*  ei = d_in[1];
    const float* W1 = (const float*)d_in[2];
    const float* b1 = (const float*)d_in[3];
    const float* Wl = (const float*)d_in[4];
    const float* bl = (const float*)d_in[5];
    const float* Wr = (const float*)d_in[6];
    const float* br = (const float*)d_in[7];
    const float* W3 = (const float*)d_in[8];
    const float* b3 = (const float*)d_in[9];
    float* out = (float*)d_out;

    // wpack: plain launch (firewalls consecutive graph replays)
    k_wpack<<<360, 256>>>(W1);
    launch_pdl(k_gemm_count, dim3(96, KSPL + 8), dim3(256), x, ei);
    launch_pdl(k_gcn,  dim3((EE * 4) / 256), dim3(256), ei);
    launch_pdl(k_h_z,  dim3(NN / 8), dim3(256), b1, Wr);
    launch_pdl(k_sage, dim3((EE * 2) / 256), dim3(256), ei);
    launch_pdl(k_head, dim3((NN + 255) / 256), dim3(256), Wl, bl, br, W3, b3, out);
}